// round 13
// baseline (speedup 1.0000x reference)
#include <cuda_runtime.h>
#include <cstddef>

// Problem constants
#define BTOT   262144
#define NT     128          // threads per CTA (4 warps)
#define NROWS  128          // rows per tile (16 groups of 8 threads x 8 rows)
#define NPASS  (BTOT / NROWS)   // 2048
#define WSTR   68           // weight SMEM row stride in floats (16B aligned, conflict-free)

// SMEM layout (floats)
// wf[3]:  wf[l][j*WSTR+k] = W_l[j][k+1]     forward, slot-major      (13056)
// wb[3]:  wb[l][k*WSTR+j] = W_l[j][k+1]     backward (transposed)    (13056)
// cv[3][64]: b + t*W[:,0] folded (used by fwd layer 2)               (192)
// w0c[2][64]: W_l[j][0]  for seq layers 0,1                          (128)
// bia[2][64]: b_l[j]     for seq layers 0,1                          (128)
// bufA/bufB/bufE: INTERLEAVED row-pair buffers: [64 pairs][64 k][2]  (3*8192)
#define OFF_WB   13056
#define OFF_C    26112
#define OFF_W0C  26304
#define OFF_BIA  26432
#define OFF_A    26560
#define OFF_B    34752
#define OFF_E    42944
#define SMEM_FLOATS 51136
#define SMEM_BYTES  (SMEM_FLOATS * 4)   // 204,544 B

typedef unsigned long long ull;
struct __align__(16) u64x2 { ull a, b; };

// packed fp32x2 FMA: two INDEPENDENT IEEE fp32 fma ops (lo, hi halves).
// With halves = (row_i, row_{i+1}), each half is a bit-exact sequential chain.
__device__ __forceinline__ void ffma2(ull& d, ull x, ull y) {
    asm("fma.rn.f32x2 %0, %1, %2, %0;" : "+l"(d) : "l"(x), "l"(y));
}
__device__ __forceinline__ ull addf2(ull a, ull b) {
    ull r; asm("add.rn.f32x2 %0, %1, %2;" : "=l"(r) : "l"(a), "l"(b)); return r;
}
__device__ __forceinline__ ull splat2(float f) {
    ull r; asm("mov.b64 %0, {%1, %1};" : "=l"(r) : "f"(f)); return r;
}
__device__ __forceinline__ ull pk(float lo, float hi) {
    ull r; asm("mov.b64 %0, {%1, %2};" : "=l"(r) : "f"(lo), "f"(hi)); return r;
}
__device__ __forceinline__ void unpk(ull v, float& lo, float& hi) {
    asm("mov.b64 {%0, %1}, %2;" : "=f"(lo), "=f"(hi) : "l"(v));
}

// Quad-pair GEMV: for this thread's 8 slots s = p + 8*jj, for 4 row-pairs
// stored interleaved at act + q*128 (q = 0..3):
//   acc[q][jj].half = init[jj].half + sum_{k ascending} a_q[k]*M[s*WSTR+k]
// Each f32x2 half is a strictly sequential fp32 chain -> reference order.
__device__ __forceinline__ void gemv_quad(const float* __restrict__ M,
                                          const float* __restrict__ act,
                                          int p, const ull init[8],
                                          ull acc[4][8]) {
#pragma unroll
    for (int q = 0; q < 4; q++)
#pragma unroll
        for (int jj = 0; jj < 8; jj++) acc[q][jj] = init[jj];
    const float* mrow = M + p * WSTR;
#pragma unroll 2
    for (int kb = 0; kb < 16; kb++) {
        u64x2 h[4][2];
#pragma unroll
        for (int q = 0; q < 4; q++) {
            h[q][0] = *reinterpret_cast<const u64x2*>(act + q * 128 + 8 * kb);      // k,k+1
            h[q][1] = *reinterpret_cast<const u64x2*>(act + q * 128 + 8 * kb + 4);  // k+2,k+3
        }
#pragma unroll
        for (int jj = 0; jj < 8; jj++) {
            const float4 wv =
                *reinterpret_cast<const float4*>(mrow + jj * (8 * WSTR) + 4 * kb);
            ull wx = splat2(wv.x), wy = splat2(wv.y);
            ull wz = splat2(wv.z), ww = splat2(wv.w);
#pragma unroll
            for (int q = 0; q < 4; q++) {
                ffma2(acc[q][jj], h[q][0].a, wx);
                ffma2(acc[q][jj], h[q][0].b, wy);
                ffma2(acc[q][jj], h[q][1].a, wz);
                ffma2(acc[q][jj], h[q][1].b, ww);
            }
        }
    }
}

__global__ void __launch_bounds__(NT, 1)
ode_kernel(const float* __restrict__ gt, const float* __restrict__ gz,
           const float* __restrict__ ge,
           const float* __restrict__ W0, const float* __restrict__ b0,
           const float* __restrict__ W1, const float* __restrict__ b1,
           const float* __restrict__ W2, const float* __restrict__ b2,
           float* __restrict__ out) {
    extern __shared__ float sm[];
    float* wf   = sm;
    float* wb   = sm + OFF_WB;
    float* cv   = sm + OFF_C;
    float* w0c  = sm + OFF_W0C;
    float* bia  = sm + OFF_BIA;
    float* bufA = sm + OFF_A;
    float* bufB = sm + OFF_B;
    float* bufE = sm + OFF_E;

    const int tid = threadIdx.x;
    const float tval = gt[0];

    // ---- stage weights
    const float* Ws[3] = {W0, W1, W2};
#pragma unroll
    for (int l = 0; l < 3; l++) {
        const float* W = Ws[l];
        for (int idx = tid; idx < 64 * 64; idx += NT) {
            int j = idx >> 6, k = idx & 63;
            float wgt = W[j * 65 + k + 1];
            wf[l * 4352 + j * WSTR + k] = wgt;
            wb[l * 4352 + k * WSTR + j] = wgt;
        }
    }
    for (int idx = tid; idx < 192; idx += NT) {
        int l = idx >> 6, j = idx & 63;
        const float* W  = Ws[l];
        const float* bb = (l == 0) ? b0 : (l == 1) ? b1 : b2;
        cv[idx] = bb[j] + tval * W[j * 65];
    }
    if (tid < 128) {
        int l = tid >> 6, j = tid & 63;
        const float* W  = l ? W1 : W0;
        w0c[tid] = W[j * 65];
        bia[tid] = l ? b1[j] : b0[j];
    }
    __syncthreads();

    const int p    = tid & 7;        // output slot within group
    const int g    = tid >> 3;       // group id (0..15), owns rows 8g..8g+7
    const int qb   = 4 * g;          // first pair index (pairs qb..qb+3)
    const int w    = tid >> 5;       // warp id (owns rows 32w..32w+31 = pairs 16w..16w+15)
    const int lane = tid & 31;

    const float* A = bufA + qb * 128;
    const float* B = bufB + qb * 128;
    const float* E = bufE + qb * 128;
    float* outD = out + (size_t)BTOT * 64;

    for (int tile = blockIdx.x; tile < NPASS; tile += gridDim.x) {
        const int rowBase = tile * NROWS;

        // ---- stage z -> bufA, e -> bufE, interleaved by row pair (warp-local: 16 pairs/warp)
#pragma unroll
        for (int it = 0; it < 8; it++) {
            const int pairI = w * 16 + it * 2 + (lane >> 4);
            const int c     = lane & 15;
            const size_t g0 = (size_t)(rowBase + 2 * pairI) * 64 + 4 * c;
            float4 za = *reinterpret_cast<const float4*>(gz + g0);
            float4 zb = *reinterpret_cast<const float4*>(gz + g0 + 64);
            u64x2 v1, v2;
            v1.a = pk(za.x, zb.x); v1.b = pk(za.y, zb.y);
            v2.a = pk(za.z, zb.z); v2.b = pk(za.w, zb.w);
            *reinterpret_cast<u64x2*>(bufA + pairI * 128 + 8 * c)     = v1;
            *reinterpret_cast<u64x2*>(bufA + pairI * 128 + 8 * c + 4) = v2;
            float4 ea = *reinterpret_cast<const float4*>(ge + g0);
            float4 eb = *reinterpret_cast<const float4*>(ge + g0 + 64);
            v1.a = pk(ea.x, eb.x); v1.b = pk(ea.y, eb.y);
            v2.a = pk(ea.z, eb.z); v2.b = pk(ea.w, eb.w);
            *reinterpret_cast<u64x2*>(bufE + pairI * 128 + 8 * c)     = v1;
            *reinterpret_cast<u64x2*>(bufE + pairI * 128 + 8 * c + 4) = v2;
        }
        __syncwarp();

        ull init[8], acc[4][8];
        unsigned m0[4] = {0, 0, 0, 0}, m1[4] = {0, 0, 0, 0};

        // ---- forward layer 0 (ref-order per half): z(A) -> h0(B), masks m0
#pragma unroll
        for (int jj = 0; jj < 8; jj++)
            init[jj] = splat2(__fmaf_rn(tval, w0c[p + 8 * jj], 0.0f));
        gemv_quad(wf, A, p, init, acc);
#pragma unroll
        for (int jj = 0; jj < 8; jj++) {
            ull bsp = splat2(bia[p + 8 * jj]);
#pragma unroll
            for (int q = 0; q < 4; q++) {
                float lo, hi;
                unpk(addf2(acc[q][jj], bsp), lo, hi);
                m0[q] |= ((lo > 0.0f) ? 1u : 0u) << jj;
                m0[q] |= ((hi > 0.0f) ? 1u : 0u) << (jj + 8);
                *reinterpret_cast<ull*>(bufB + (qb + q) * 128 + 2 * (p + 8 * jj)) =
                    pk(fmaxf(lo, 0.0f), fmaxf(hi, 0.0f));
            }
        }
        __syncwarp();

        // ---- forward layer 1 (ref-order per half): h0(B) -> h1(A), masks m1
#pragma unroll
        for (int jj = 0; jj < 8; jj++)
            init[jj] = splat2(__fmaf_rn(tval, w0c[64 + p + 8 * jj], 0.0f));
        gemv_quad(wf + 4352, B, p, init, acc);
#pragma unroll
        for (int jj = 0; jj < 8; jj++) {
            ull bsp = splat2(bia[64 + p + 8 * jj]);
#pragma unroll
            for (int q = 0; q < 4; q++) {
                float lo, hi;
                unpk(addf2(acc[q][jj], bsp), lo, hi);
                m1[q] |= ((lo > 0.0f) ? 1u : 0u) << jj;
                m1[q] |= ((hi > 0.0f) ? 1u : 0u) << (jj + 8);
                *reinterpret_cast<ull*>(bufA + (qb + q) * 128 + 2 * (p + 8 * jj)) =
                    pk(fmaxf(lo, 0.0f), fmaxf(hi, 0.0f));
            }
        }
        __syncwarp();

        // ---- forward layer 2 (no relu): h1(A) -> z_dot(B)
#pragma unroll
        for (int jj = 0; jj < 8; jj++)
            init[jj] = splat2(cv[128 + p + 8 * jj]);
        gemv_quad(wf + 8704, A, p, init, acc);
#pragma unroll
        for (int jj = 0; jj < 8; jj++)
#pragma unroll
            for (int q = 0; q < 4; q++)
                *reinterpret_cast<ull*>(bufB + (qb + q) * 128 + 2 * (p + 8 * jj)) =
                    acc[q][jj];
        __syncwarp();

        // ---- flush z_dot: deinterleave B -> global (coalesced)
#pragma unroll
        for (int it = 0; it < 8; it++) {
            const int pairI = w * 16 + it * 2 + (lane >> 4);
            const int c     = lane & 15;
            u64x2 v1 = *reinterpret_cast<const u64x2*>(bufB + pairI * 128 + 8 * c);
            u64x2 v2 = *reinterpret_cast<const u64x2*>(bufB + pairI * 128 + 8 * c + 4);
            float4 ra, rb;
            unpk(v1.a, ra.x, rb.x); unpk(v1.b, ra.y, rb.y);
            unpk(v2.a, ra.z, rb.z); unpk(v2.b, ra.w, rb.w);
            const size_t g0 = (size_t)(rowBase + 2 * pairI) * 64 + 4 * c;
            *reinterpret_cast<float4*>(out + g0)      = ra;
            *reinterpret_cast<float4*>(out + g0 + 64) = rb;
        }

        // ---- backward layer 2: g1 = W2[:,1:]^T e, mask m1  (E -> A)
#pragma unroll
        for (int jj = 0; jj < 8; jj++) init[jj] = 0ull;
        gemv_quad(wb + 8704, E, p, init, acc);
#pragma unroll
        for (int jj = 0; jj < 8; jj++)
#pragma unroll
            for (int q = 0; q < 4; q++) {
                float lo, hi;
                unpk(acc[q][jj], lo, hi);
                lo = ((m1[q] >> jj) & 1) ? lo : 0.0f;
                hi = ((m1[q] >> (jj + 8)) & 1) ? hi : 0.0f;
                *reinterpret_cast<ull*>(bufA + (qb + q) * 128 + 2 * (p + 8 * jj)) =
                    pk(lo, hi);
            }
        __syncwarp();

        // ---- backward layer 1: g0 = W1[:,1:]^T g1, mask m0  (A -> B)
        gemv_quad(wb + 4352, A, p, init, acc);
#pragma unroll
        for (int jj = 0; jj < 8; jj++)
#pragma unroll
            for (int q = 0; q < 4; q++) {
                float lo, hi;
                unpk(acc[q][jj], lo, hi);
                lo = ((m0[q] >> jj) & 1) ? lo : 0.0f;
                hi = ((m0[q] >> (jj + 8)) & 1) ? hi : 0.0f;
                *reinterpret_cast<ull*>(bufB + (qb + q) * 128 + 2 * (p + 8 * jj)) =
                    pk(lo, hi);
            }
        __syncwarp();

        // ---- backward layer 0: gz = W0[:,1:]^T g0, then div = <gz, e>
        gemv_quad(wb, B, p, init, acc);
        ull dq[4] = {0ull, 0ull, 0ull, 0ull};
#pragma unroll
        for (int jj = 0; jj < 8; jj++)
#pragma unroll
            for (int q = 0; q < 4; q++)
                ffma2(dq[q], acc[q][jj],
                      *reinterpret_cast<const ull*>(bufE + (qb + q) * 128 +
                                                    2 * (p + 8 * jj)));
        float d[8];
#pragma unroll
        for (int q = 0; q < 4; q++) unpk(dq[q], d[2 * q], d[2 * q + 1]);
#pragma unroll
        for (int ofs = 4; ofs > 0; ofs >>= 1)
#pragma unroll
            for (int r = 0; r < 8; r++)
                d[r] += __shfl_down_sync(0xffffffffu, d[r], ofs, 8);
        if (p == 0) {
#pragma unroll
            for (int r = 0; r < 8; r++)
                outD[rowBase + 8 * g + r] = -d[r];
        }
        __syncwarp();
    }
}

extern "C" void kernel_launch(void* const* d_in, const int* in_sizes, int n_in,
                              void* d_out, int out_size) {
    // metadata order: t, z, e, W0, b0, W1, b1, W2, b2 (all float32)
    const float* t  = (const float*)d_in[0];
    const float* z  = (const float*)d_in[1];
    const float* e  = (const float*)d_in[2];
    const float* W0 = (const float*)d_in[3];
    const float* b0 = (const float*)d_in[4];
    const float* W1 = (const float*)d_in[5];
    const float* b1 = (const float*)d_in[6];
    const float* W2 = (const float*)d_in[7];
    const float* b2 = (const float*)d_in[8];
    float* out = (float*)d_out;   // [B*64] z_dot followed by [B] of -div

    (void)in_sizes; (void)n_in; (void)out_size;

    cudaFuncSetAttribute(ode_kernel,
                         cudaFuncAttributeMaxDynamicSharedMemorySize, SMEM_BYTES);

    int dev = 0;
    cudaGetDevice(&dev);
    int sms = 148;
    cudaDeviceGetAttribute(&sms, cudaDevAttrMultiProcessorCount, dev);
    if (sms < 1) sms = 148;
    if (sms > NPASS) sms = NPASS;

    ode_kernel<<<sms, NT, SMEM_BYTES>>>(t, z, e, W0, b0, W1, b1, W2, b2, out);
}

// round 14
// speedup vs baseline: 1.3428x; 1.3428x over previous
#include <cuda_runtime.h>
#include <cstddef>

// Problem constants
#define BTOT   262144
#define NT     128          // threads per CTA (4 warps)
#define NROWS  128          // rows per tile (16 groups of 8 threads x 8 rows)
#define NPASS  (BTOT / NROWS)   // 2048
#define WSTR   68           // weight SMEM row stride in floats (16B aligned, conflict-free)

// SMEM layout (floats)
// wf[3]:  wf[l][j*WSTR+k] = W_l[j][k+1]     forward, slot-major      (13056)
// wb[3]:  wb[l][k*WSTR+j] = W_l[j][k+1]     backward (transposed)    (13056)
// cv[3][64]: b + t*W[:,0] folded (fwd layer 2 init)                  (192)
// iv[2][64]: fma(t, W_l[j][0], 0) chain-start for seq layers 0,1    (128)
// bia[2][64]: b_l[j] for seq layers 0,1 (added after chain)          (128)
// bufA/bufB/bufE: INTERLEAVED row-pair buffers: [64 pairs][64 k][2]  (3*8192)
#define OFF_WB   13056
#define OFF_C    26112
#define OFF_IV   26304
#define OFF_BIA  26432
#define OFF_A    26560
#define OFF_B    34752
#define OFF_E    42944
#define SMEM_FLOATS 51136
#define SMEM_BYTES  (SMEM_FLOATS * 4)   // 204,544 B

typedef unsigned long long ull;
struct __align__(16) u64x2 { ull a, b; };

// packed fp32x2 FMA: two INDEPENDENT IEEE fp32 fma ops (lo, hi halves).
// With halves = (row_i, row_{i+1}), each half is a bit-exact sequential chain.
__device__ __forceinline__ void ffma2(ull& d, ull x, ull y) {
    asm("fma.rn.f32x2 %0, %1, %2, %0;" : "+l"(d) : "l"(x), "l"(y));
}
__device__ __forceinline__ ull addf2(ull a, ull b) {
    ull r; asm("add.rn.f32x2 %0, %1, %2;" : "=l"(r) : "l"(a), "l"(b)); return r;
}
__device__ __forceinline__ ull splat2(float f) {
    ull r; asm("mov.b64 %0, {%1, %1};" : "=l"(r) : "f"(f)); return r;
}
__device__ __forceinline__ ull pk(float lo, float hi) {
    ull r; asm("mov.b64 %0, {%1, %2};" : "=l"(r) : "f"(lo), "f"(hi)); return r;
}
__device__ __forceinline__ void unpk(ull v, float& lo, float& hi) {
    asm("mov.b64 {%0, %1}, %2;" : "=f"(lo), "=f"(hi) : "l"(v));
}

// Quad-pair GEMV core: for this thread's 8 slots s = p + 8*jj, for 4 row-pairs
// stored interleaved at act + q*128 (q = 0..3):
//   acc[q][jj].half += sum_{k ascending} a_q[k] * M[s*WSTR + k]
// Caller pre-initializes acc (chain start). Each f32x2 half is a strictly
// sequential ascending-k fp32 chain -> reference accumulation order.
// unroll 1: single staging generation (32 regs) -- register-lean by design.
__device__ __forceinline__ void gemv_quad(const float* __restrict__ M,
                                          const float* __restrict__ act,
                                          int p, ull acc[4][8]) {
    const float* mrow = M + p * WSTR;
#pragma unroll 1
    for (int kb = 0; kb < 16; kb++) {
        const u64x2 h0a = *reinterpret_cast<const u64x2*>(act + 0 * 128 + 8 * kb);
        const u64x2 h0b = *reinterpret_cast<const u64x2*>(act + 0 * 128 + 8 * kb + 4);
        const u64x2 h1a = *reinterpret_cast<const u64x2*>(act + 1 * 128 + 8 * kb);
        const u64x2 h1b = *reinterpret_cast<const u64x2*>(act + 1 * 128 + 8 * kb + 4);
        const u64x2 h2a = *reinterpret_cast<const u64x2*>(act + 2 * 128 + 8 * kb);
        const u64x2 h2b = *reinterpret_cast<const u64x2*>(act + 2 * 128 + 8 * kb + 4);
        const u64x2 h3a = *reinterpret_cast<const u64x2*>(act + 3 * 128 + 8 * kb);
        const u64x2 h3b = *reinterpret_cast<const u64x2*>(act + 3 * 128 + 8 * kb + 4);
#pragma unroll
        for (int jj = 0; jj < 8; jj++) {
            const float4 wv =
                *reinterpret_cast<const float4*>(mrow + jj * (8 * WSTR) + 4 * kb);
            ull wx = splat2(wv.x), wy = splat2(wv.y);
            ull wz = splat2(wv.z), ww = splat2(wv.w);
            ffma2(acc[0][jj], h0a.a, wx);
            ffma2(acc[0][jj], h0a.b, wy);
            ffma2(acc[0][jj], h0b.a, wz);
            ffma2(acc[0][jj], h0b.b, ww);
            ffma2(acc[1][jj], h1a.a, wx);
            ffma2(acc[1][jj], h1a.b, wy);
            ffma2(acc[1][jj], h1b.a, wz);
            ffma2(acc[1][jj], h1b.b, ww);
            ffma2(acc[2][jj], h2a.a, wx);
            ffma2(acc[2][jj], h2a.b, wy);
            ffma2(acc[2][jj], h2b.a, wz);
            ffma2(acc[2][jj], h2b.b, ww);
            ffma2(acc[3][jj], h3a.a, wx);
            ffma2(acc[3][jj], h3a.b, wy);
            ffma2(acc[3][jj], h3b.a, wz);
            ffma2(acc[3][jj], h3b.b, ww);
        }
    }
}

__global__ void __launch_bounds__(NT, 1)
ode_kernel(const float* __restrict__ gt, const float* __restrict__ gz,
           const float* __restrict__ ge,
           const float* __restrict__ W0, const float* __restrict__ b0,
           const float* __restrict__ W1, const float* __restrict__ b1,
           const float* __restrict__ W2, const float* __restrict__ b2,
           float* __restrict__ out) {
    extern __shared__ float sm[];
    float* wf   = sm;
    float* wb   = sm + OFF_WB;
    float* cv   = sm + OFF_C;
    float* iv   = sm + OFF_IV;
    float* bia  = sm + OFF_BIA;
    float* bufA = sm + OFF_A;
    float* bufB = sm + OFF_B;
    float* bufE = sm + OFF_E;

    const int tid = threadIdx.x;
    const float tval = gt[0];

    // ---- stage weights
    const float* Ws[3] = {W0, W1, W2};
#pragma unroll 1
    for (int l = 0; l < 3; l++) {
        const float* W = Ws[l];
        for (int idx = tid; idx < 64 * 64; idx += NT) {
            int j = idx >> 6, k = idx & 63;
            float wgt = W[j * 65 + k + 1];
            wf[l * 4352 + j * WSTR + k] = wgt;
            wb[l * 4352 + k * WSTR + j] = wgt;
        }
    }
    for (int idx = tid; idx < 192; idx += NT) {
        int l = idx >> 6, j = idx & 63;
        const float* W  = Ws[l];
        const float* bb = (l == 0) ? b0 : (l == 1) ? b1 : b2;
        cv[idx] = bb[j] + tval * W[j * 65];
    }
    if (tid < 128) {
        int l = tid >> 6, j = tid & 63;
        const float* W  = l ? W1 : W0;
        iv[tid]  = __fmaf_rn(tval, W[j * 65], 0.0f);  // exact chain-start value
        bia[tid] = l ? b1[j] : b0[j];
    }
    __syncthreads();

    const int p    = tid & 7;        // output slot within group
    const int g    = tid >> 3;       // group id (0..15), owns rows 8g..8g+7
    const int qb   = 4 * g;          // first pair index (pairs qb..qb+3)
    const int w    = tid >> 5;       // warp id (owns pairs 16w..16w+15)
    const int lane = tid & 31;

    const float* A = bufA + qb * 128;
    const float* B = bufB + qb * 128;
    const float* E = bufE + qb * 128;
    float* outD = out + (size_t)BTOT * 64;

    for (int tile = blockIdx.x; tile < NPASS; tile += gridDim.x) {
        const int rowBase = tile * NROWS;

        // ---- stage z -> bufA, e -> bufE, interleaved by row pair (warp-local)
#pragma unroll 1
        for (int it = 0; it < 8; it++) {
            const int pairI = w * 16 + it * 2 + (lane >> 4);
            const int c     = lane & 15;
            const size_t g0 = (size_t)(rowBase + 2 * pairI) * 64 + 4 * c;
            float4 za = *reinterpret_cast<const float4*>(gz + g0);
            float4 zb = *reinterpret_cast<const float4*>(gz + g0 + 64);
            u64x2 v1, v2;
            v1.a = pk(za.x, zb.x); v1.b = pk(za.y, zb.y);
            v2.a = pk(za.z, zb.z); v2.b = pk(za.w, zb.w);
            *reinterpret_cast<u64x2*>(bufA + pairI * 128 + 8 * c)     = v1;
            *reinterpret_cast<u64x2*>(bufA + pairI * 128 + 8 * c + 4) = v2;
            float4 ea = *reinterpret_cast<const float4*>(ge + g0);
            float4 eb = *reinterpret_cast<const float4*>(ge + g0 + 64);
            v1.a = pk(ea.x, eb.x); v1.b = pk(ea.y, eb.y);
            v2.a = pk(ea.z, eb.z); v2.b = pk(ea.w, eb.w);
            *reinterpret_cast<u64x2*>(bufE + pairI * 128 + 8 * c)     = v1;
            *reinterpret_cast<u64x2*>(bufE + pairI * 128 + 8 * c + 4) = v2;
        }
        __syncwarp();

        ull acc[4][8];
        unsigned m0[4], m1[4];

        // ---- forward layer 0 (ref-order per half): z(A) -> h0(B), masks m0
#pragma unroll
        for (int jj = 0; jj < 8; jj++) {
            ull ivs = splat2(iv[p + 8 * jj]);
            acc[0][jj] = ivs; acc[1][jj] = ivs; acc[2][jj] = ivs; acc[3][jj] = ivs;
        }
        gemv_quad(wf, A, p, acc);
#pragma unroll
        for (int q = 0; q < 4; q++) m0[q] = 0u;
#pragma unroll
        for (int jj = 0; jj < 8; jj++) {
            ull bsp = splat2(bia[p + 8 * jj]);
#pragma unroll
            for (int q = 0; q < 4; q++) {
                float lo, hi;
                unpk(addf2(acc[q][jj], bsp), lo, hi);
                m0[q] |= ((lo > 0.0f) ? 1u : 0u) << jj;
                m0[q] |= ((hi > 0.0f) ? 1u : 0u) << (jj + 8);
                *reinterpret_cast<ull*>(bufB + (qb + q) * 128 + 2 * (p + 8 * jj)) =
                    pk(fmaxf(lo, 0.0f), fmaxf(hi, 0.0f));
            }
        }
        __syncwarp();

        // ---- forward layer 1 (ref-order per half): h0(B) -> h1(A), masks m1
#pragma unroll
        for (int jj = 0; jj < 8; jj++) {
            ull ivs = splat2(iv[64 + p + 8 * jj]);
            acc[0][jj] = ivs; acc[1][jj] = ivs; acc[2][jj] = ivs; acc[3][jj] = ivs;
        }
        gemv_quad(wf + 4352, B, p, acc);
#pragma unroll
        for (int q = 0; q < 4; q++) m1[q] = 0u;
#pragma unroll
        for (int jj = 0; jj < 8; jj++) {
            ull bsp = splat2(bia[64 + p + 8 * jj]);
#pragma unroll
            for (int q = 0; q < 4; q++) {
                float lo, hi;
                unpk(addf2(acc[q][jj], bsp), lo, hi);
                m1[q] |= ((lo > 0.0f) ? 1u : 0u) << jj;
                m1[q] |= ((hi > 0.0f) ? 1u : 0u) << (jj + 8);
                *reinterpret_cast<ull*>(bufA + (qb + q) * 128 + 2 * (p + 8 * jj)) =
                    pk(fmaxf(lo, 0.0f), fmaxf(hi, 0.0f));
            }
        }
        __syncwarp();

        // ---- forward layer 2 (no relu): h1(A) -> z_dot(B)
#pragma unroll
        for (int jj = 0; jj < 8; jj++) {
            ull cvs = splat2(cv[128 + p + 8 * jj]);
            acc[0][jj] = cvs; acc[1][jj] = cvs; acc[2][jj] = cvs; acc[3][jj] = cvs;
        }
        gemv_quad(wf + 8704, A, p, acc);
#pragma unroll
        for (int jj = 0; jj < 8; jj++)
#pragma unroll
            for (int q = 0; q < 4; q++)
                *reinterpret_cast<ull*>(bufB + (qb + q) * 128 + 2 * (p + 8 * jj)) =
                    acc[q][jj];
        __syncwarp();

        // ---- flush z_dot: deinterleave B -> global (coalesced)
#pragma unroll 1
        for (int it = 0; it < 8; it++) {
            const int pairI = w * 16 + it * 2 + (lane >> 4);
            const int c     = lane & 15;
            u64x2 v1 = *reinterpret_cast<const u64x2*>(bufB + pairI * 128 + 8 * c);
            u64x2 v2 = *reinterpret_cast<const u64x2*>(bufB + pairI * 128 + 8 * c + 4);
            float4 ra, rb;
            unpk(v1.a, ra.x, rb.x); unpk(v1.b, ra.y, rb.y);
            unpk(v2.a, ra.z, rb.z); unpk(v2.b, ra.w, rb.w);
            const size_t g0 = (size_t)(rowBase + 2 * pairI) * 64 + 4 * c;
            *reinterpret_cast<float4*>(out + g0)      = ra;
            *reinterpret_cast<float4*>(out + g0 + 64) = rb;
        }

        // ---- backward layer 2: g1 = W2[:,1:]^T e, mask m1  (E -> A)
#pragma unroll
        for (int jj = 0; jj < 8; jj++) {
            acc[0][jj] = 0ull; acc[1][jj] = 0ull; acc[2][jj] = 0ull; acc[3][jj] = 0ull;
        }
        gemv_quad(wb + 8704, E, p, acc);
#pragma unroll
        for (int jj = 0; jj < 8; jj++)
#pragma unroll
            for (int q = 0; q < 4; q++) {
                float lo, hi;
                unpk(acc[q][jj], lo, hi);
                lo = ((m1[q] >> jj) & 1) ? lo : 0.0f;
                hi = ((m1[q] >> (jj + 8)) & 1) ? hi : 0.0f;
                *reinterpret_cast<ull*>(bufA + (qb + q) * 128 + 2 * (p + 8 * jj)) =
                    pk(lo, hi);
            }
        __syncwarp();

        // ---- backward layer 1: g0 = W1[:,1:]^T g1, mask m0  (A -> B)
#pragma unroll
        for (int jj = 0; jj < 8; jj++) {
            acc[0][jj] = 0ull; acc[1][jj] = 0ull; acc[2][jj] = 0ull; acc[3][jj] = 0ull;
        }
        gemv_quad(wb + 4352, A, p, acc);
#pragma unroll
        for (int jj = 0; jj < 8; jj++)
#pragma unroll
            for (int q = 0; q < 4; q++) {
                float lo, hi;
                unpk(acc[q][jj], lo, hi);
                lo = ((m0[q] >> jj) & 1) ? lo : 0.0f;
                hi = ((m0[q] >> (jj + 8)) & 1) ? hi : 0.0f;
                *reinterpret_cast<ull*>(bufB + (qb + q) * 128 + 2 * (p + 8 * jj)) =
                    pk(lo, hi);
            }
        __syncwarp();

        // ---- backward layer 0: gz = W0[:,1:]^T g0, then div = <gz, e>
#pragma unroll
        for (int jj = 0; jj < 8; jj++) {
            acc[0][jj] = 0ull; acc[1][jj] = 0ull; acc[2][jj] = 0ull; acc[3][jj] = 0ull;
        }
        gemv_quad(wb, B, p, acc);
        ull dq0 = 0ull, dq1 = 0ull, dq2 = 0ull, dq3 = 0ull;
#pragma unroll
        for (int jj = 0; jj < 8; jj++) {
            ffma2(dq0, acc[0][jj],
                  *reinterpret_cast<const ull*>(bufE + (qb + 0) * 128 + 2 * (p + 8 * jj)));
            ffma2(dq1, acc[1][jj],
                  *reinterpret_cast<const ull*>(bufE + (qb + 1) * 128 + 2 * (p + 8 * jj)));
            ffma2(dq2, acc[2][jj],
                  *reinterpret_cast<const ull*>(bufE + (qb + 2) * 128 + 2 * (p + 8 * jj)));
            ffma2(dq3, acc[3][jj],
                  *reinterpret_cast<const ull*>(bufE + (qb + 3) * 128 + 2 * (p + 8 * jj)));
        }
        float d[8];
        unpk(dq0, d[0], d[1]);
        unpk(dq1, d[2], d[3]);
        unpk(dq2, d[4], d[5]);
        unpk(dq3, d[6], d[7]);
#pragma unroll
        for (int ofs = 4; ofs > 0; ofs >>= 1)
#pragma unroll
            for (int r = 0; r < 8; r++)
                d[r] += __shfl_down_sync(0xffffffffu, d[r], ofs, 8);
        if (p == 0) {
#pragma unroll
            for (int r = 0; r < 8; r++)
                outD[rowBase + 8 * g + r] = -d[r];
        }
        __syncwarp();
    }
}

extern "C" void kernel_launch(void* const* d_in, const int* in_sizes, int n_in,
                              void* d_out, int out_size) {
    // metadata order: t, z, e, W0, b0, W1, b1, W2, b2 (all float32)
    const float* t  = (const float*)d_in[0];
    const float* z  = (const float*)d_in[1];
    const float* e  = (const float*)d_in[2];
    const float* W0 = (const float*)d_in[3];
    const float* b0 = (const float*)d_in[4];
    const float* W1 = (const float*)d_in[5];
    const float* b1 = (const float*)d_in[6];
    const float* W2 = (const float*)d_in[7];
    const float* b2 = (const float*)d_in[8];
    float* out = (float*)d_out;   // [B*64] z_dot followed by [B] of -div

    (void)in_sizes; (void)n_in; (void)out_size;

    cudaFuncSetAttribute(ode_kernel,
                         cudaFuncAttributeMaxDynamicSharedMemorySize, SMEM_BYTES);

    int dev = 0;
    cudaGetDevice(&dev);
    int sms = 148;
    cudaDeviceGetAttribute(&sms, cudaDevAttrMultiProcessorCount, dev);
    if (sms < 1) sms = 148;
    if (sms > NPASS) sms = NPASS;

    ode_kernel<<<sms, NT, SMEM_BYTES>>>(t, z, e, W0, b0, W1, b1, W2, b2, out);
}

// round 15
// speedup vs baseline: 1.9210x; 1.4306x over previous
#include <cuda_runtime.h>
#include <cstddef>

// Problem constants
#define BTOT   262144
#define NT     256          // threads per CTA (8 warps, 2 per SMSP)
#define NROWS  128          // rows per tile (32 groups of 8 threads x 4 rows)
#define NPASS  (BTOT / NROWS)   // 2048
#define WSTR   68           // weight SMEM row stride in floats (16B aligned, conflict-free)

// SMEM layout (floats) -- JVP formulation: forward weights ONLY (no wb!)
// wf[3]:  wf[l][j*WSTR+k] = W_l[j][k+1]                              (13056)
// cv[3][64]: b + t*W[:,0] folded (fwd layer 2 init)                  (192)
// iv[2][64]: fma(t, W_l[j][0], 0) chain-start for seq layers 0,1    (128)
// bia[2][64]: b_l[j] for seq layers 0,1 (added after chain)          (128)
// bufA/bufB: primal ping-pong, bufE: e (preserved), bufF: tangent
//   INTERLEAVED row-pair buffers: [64 pairs][64 k][2]                (4*8192)
#define OFF_C    13056
#define OFF_IV   13248
#define OFF_BIA  13376
#define OFF_A    13504
#define OFF_B    21696
#define OFF_E    29888
#define OFF_F    38080
#define SMEM_FLOATS 46272
#define SMEM_BYTES  (SMEM_FLOATS * 4)   // 185,088 B

typedef unsigned long long ull;
struct __align__(16) u64x2 { ull a, b; };

// packed fp32x2 FMA: two INDEPENDENT IEEE fp32 fma ops (lo, hi halves).
// Halves = (row_i, row_{i+1}): each half is a bit-exact sequential chain.
__device__ __forceinline__ void ffma2(ull& d, ull x, ull y) {
    asm("fma.rn.f32x2 %0, %1, %2, %0;" : "+l"(d) : "l"(x), "l"(y));
}
__device__ __forceinline__ ull addf2(ull a, ull b) {
    ull r; asm("add.rn.f32x2 %0, %1, %2;" : "=l"(r) : "l"(a), "l"(b)); return r;
}
__device__ __forceinline__ ull splat2(float f) {
    ull r; asm("mov.b64 %0, {%1, %1};" : "=l"(r) : "f"(f)); return r;
}
__device__ __forceinline__ ull pk(float lo, float hi) {
    ull r; asm("mov.b64 %0, {%1, %2};" : "=l"(r) : "f"(lo), "f"(hi)); return r;
}
__device__ __forceinline__ void unpk(ull v, float& lo, float& hi) {
    asm("mov.b64 {%0, %1}, %2;" : "=f"(lo), "=f"(hi) : "l"(v));
}

// Fused primal+tangent GEMV: each weight float4 (loaded ONCE) feeds BOTH
// streams. For this thread's 8 slots s = p + 8*jj, for 2 row-pairs each of
// primal (aP) and tangent (aT) activations (interleaved pair format):
//   accP/accT[pair][jj].half += sum_{k ascending} a[k] * M[s*WSTR + k]
// Each f32x2 half is a strictly sequential ascending-k fp32 chain.
__device__ __forceinline__ void gemv_fused(const float* __restrict__ M,
                                           const float* __restrict__ aP,
                                           const float* __restrict__ aT,
                                           int p,
                                           ull accP0[8], ull accP1[8],
                                           ull accT0[8], ull accT1[8]) {
    const float* mrow = M + p * WSTR;
#pragma unroll 1
    for (int kb = 0; kb < 16; kb++) {
        const u64x2 hP0a = *reinterpret_cast<const u64x2*>(aP + 8 * kb);
        const u64x2 hP0b = *reinterpret_cast<const u64x2*>(aP + 8 * kb + 4);
        const u64x2 hP1a = *reinterpret_cast<const u64x2*>(aP + 128 + 8 * kb);
        const u64x2 hP1b = *reinterpret_cast<const u64x2*>(aP + 128 + 8 * kb + 4);
        const u64x2 hT0a = *reinterpret_cast<const u64x2*>(aT + 8 * kb);
        const u64x2 hT0b = *reinterpret_cast<const u64x2*>(aT + 8 * kb + 4);
        const u64x2 hT1a = *reinterpret_cast<const u64x2*>(aT + 128 + 8 * kb);
        const u64x2 hT1b = *reinterpret_cast<const u64x2*>(aT + 128 + 8 * kb + 4);
#pragma unroll
        for (int jj = 0; jj < 8; jj++) {
            const float4 wv =
                *reinterpret_cast<const float4*>(mrow + jj * (8 * WSTR) + 4 * kb);
            ull wx = splat2(wv.x), wy = splat2(wv.y);
            ull wz = splat2(wv.z), ww = splat2(wv.w);
            ffma2(accP0[jj], hP0a.a, wx);
            ffma2(accP0[jj], hP0a.b, wy);
            ffma2(accP0[jj], hP0b.a, wz);
            ffma2(accP0[jj], hP0b.b, ww);
            ffma2(accP1[jj], hP1a.a, wx);
            ffma2(accP1[jj], hP1a.b, wy);
            ffma2(accP1[jj], hP1b.a, wz);
            ffma2(accP1[jj], hP1b.b, ww);
            ffma2(accT0[jj], hT0a.a, wx);
            ffma2(accT0[jj], hT0a.b, wy);
            ffma2(accT0[jj], hT0b.a, wz);
            ffma2(accT0[jj], hT0b.b, ww);
            ffma2(accT1[jj], hT1a.a, wx);
            ffma2(accT1[jj], hT1a.b, wy);
            ffma2(accT1[jj], hT1b.a, wz);
            ffma2(accT1[jj], hT1b.b, ww);
        }
    }
}

__global__ void __launch_bounds__(NT, 1)
ode_kernel(const float* __restrict__ gt, const float* __restrict__ gz,
           const float* __restrict__ ge,
           const float* __restrict__ W0, const float* __restrict__ b0,
           const float* __restrict__ W1, const float* __restrict__ b1,
           const float* __restrict__ W2, const float* __restrict__ b2,
           float* __restrict__ out) {
    extern __shared__ float sm[];
    float* wf   = sm;
    float* cv   = sm + OFF_C;
    float* iv   = sm + OFF_IV;
    float* bia  = sm + OFF_BIA;
    float* bufA = sm + OFF_A;
    float* bufB = sm + OFF_B;
    float* bufE = sm + OFF_E;
    float* bufF = sm + OFF_F;

    const int tid = threadIdx.x;
    const float tval = gt[0];

    // ---- stage forward weights only
    const float* Ws[3] = {W0, W1, W2};
#pragma unroll 1
    for (int l = 0; l < 3; l++) {
        const float* W = Ws[l];
        for (int idx = tid; idx < 64 * 64; idx += NT) {
            int j = idx >> 6, k = idx & 63;
            wf[l * 4352 + j * WSTR + k] = W[j * 65 + k + 1];
        }
    }
    if (tid < 192) {
        int l = tid >> 6, j = tid & 63;
        const float* W  = Ws[l];
        const float* bb = (l == 0) ? b0 : (l == 1) ? b1 : b2;
        cv[tid] = bb[j] + tval * W[j * 65];
    }
    if (tid < 128) {
        int l = tid >> 6, j = tid & 63;
        const float* W  = l ? W1 : W0;
        iv[tid]  = __fmaf_rn(tval, W[j * 65], 0.0f);  // exact chain-start
        bia[tid] = l ? b1[j] : b0[j];
    }
    __syncthreads();

    const int p    = tid & 7;        // output slot within group
    const int g    = tid >> 3;       // group id (0..31), owns rows 4g..4g+3
    const int q0   = 2 * g;          // pair 0 = rows 4g, 4g+1
    const int q1   = 2 * g + 1;      // pair 1 = rows 4g+2, 4g+3
    const int w    = tid >> 5;       // warp id (owns pairs 8w..8w+7)
    const int lane = tid & 31;

    const float* A = bufA + q0 * 128;
    const float* B = bufB + q0 * 128;
    const float* E = bufE + q0 * 128;
    const float* F = bufF + q0 * 128;
    float* outD = out + (size_t)BTOT * 64;

    for (int tile = blockIdx.x; tile < NPASS; tile += gridDim.x) {
        const int rowBase = tile * NROWS;

        // ---- stage z -> bufA, e -> bufE, interleaved by row pair (warp-local)
#pragma unroll 1
        for (int it = 0; it < 4; it++) {
            const int pairI = w * 8 + it * 2 + (lane >> 4);
            const int c     = lane & 15;
            const size_t g0 = (size_t)(rowBase + 2 * pairI) * 64 + 4 * c;
            float4 za = *reinterpret_cast<const float4*>(gz + g0);
            float4 zb = *reinterpret_cast<const float4*>(gz + g0 + 64);
            u64x2 v1, v2;
            v1.a = pk(za.x, zb.x); v1.b = pk(za.y, zb.y);
            v2.a = pk(za.z, zb.z); v2.b = pk(za.w, zb.w);
            *reinterpret_cast<u64x2*>(bufA + pairI * 128 + 8 * c)     = v1;
            *reinterpret_cast<u64x2*>(bufA + pairI * 128 + 8 * c + 4) = v2;
            float4 ea = *reinterpret_cast<const float4*>(ge + g0);
            float4 eb = *reinterpret_cast<const float4*>(ge + g0 + 64);
            v1.a = pk(ea.x, eb.x); v1.b = pk(ea.y, eb.y);
            v2.a = pk(ea.z, eb.z); v2.b = pk(ea.w, eb.w);
            *reinterpret_cast<u64x2*>(bufE + pairI * 128 + 8 * c)     = v1;
            *reinterpret_cast<u64x2*>(bufE + pairI * 128 + 8 * c + 4) = v2;
        }
        __syncwarp();

        ull accP0[8], accP1[8], accT0[8], accT1[8];

        // ---- layer 0 fused: primal z(A) -> h0(B) [ref-order chain, masks],
        //                     tangent e(E) -> h0'(F) [masked by primal sign]
#pragma unroll
        for (int jj = 0; jj < 8; jj++) {
            ull ivs = splat2(iv[p + 8 * jj]);
            accP0[jj] = ivs; accP1[jj] = ivs;
            accT0[jj] = 0ull; accT1[jj] = 0ull;
        }
        gemv_fused(wf, A, E, p, accP0, accP1, accT0, accT1);
#pragma unroll
        for (int jj = 0; jj < 8; jj++) {
            ull bsp = splat2(bia[p + 8 * jj]);
            float lo, hi, tl, th;
            unpk(addf2(accP0[jj], bsp), lo, hi);
            unpk(accT0[jj], tl, th);
            *reinterpret_cast<ull*>(bufB + q0 * 128 + 2 * (p + 8 * jj)) =
                pk(fmaxf(lo, 0.0f), fmaxf(hi, 0.0f));
            *reinterpret_cast<ull*>(bufF + q0 * 128 + 2 * (p + 8 * jj)) =
                pk((lo > 0.0f) ? tl : 0.0f, (hi > 0.0f) ? th : 0.0f);
            unpk(addf2(accP1[jj], bsp), lo, hi);
            unpk(accT1[jj], tl, th);
            *reinterpret_cast<ull*>(bufB + q1 * 128 + 2 * (p + 8 * jj)) =
                pk(fmaxf(lo, 0.0f), fmaxf(hi, 0.0f));
            *reinterpret_cast<ull*>(bufF + q1 * 128 + 2 * (p + 8 * jj)) =
                pk((lo > 0.0f) ? tl : 0.0f, (hi > 0.0f) ? th : 0.0f);
        }
        __syncwarp();

        // ---- layer 1 fused: primal h0(B) -> h1(A), tangent h0'(F) -> h1'(F)
        // (F updated in place: all reads precede epilogue writes in program
        //  order and the whole row group is within one warp)
#pragma unroll
        for (int jj = 0; jj < 8; jj++) {
            ull ivs = splat2(iv[64 + p + 8 * jj]);
            accP0[jj] = ivs; accP1[jj] = ivs;
            accT0[jj] = 0ull; accT1[jj] = 0ull;
        }
        gemv_fused(wf + 4352, B, F, p, accP0, accP1, accT0, accT1);
#pragma unroll
        for (int jj = 0; jj < 8; jj++) {
            ull bsp = splat2(bia[64 + p + 8 * jj]);
            float lo, hi, tl, th;
            unpk(addf2(accP0[jj], bsp), lo, hi);
            unpk(accT0[jj], tl, th);
            *reinterpret_cast<ull*>(bufA + q0 * 128 + 2 * (p + 8 * jj)) =
                pk(fmaxf(lo, 0.0f), fmaxf(hi, 0.0f));
            *reinterpret_cast<ull*>(bufF + q0 * 128 + 2 * (p + 8 * jj)) =
                pk((lo > 0.0f) ? tl : 0.0f, (hi > 0.0f) ? th : 0.0f);
            unpk(addf2(accP1[jj], bsp), lo, hi);
            unpk(accT1[jj], tl, th);
            *reinterpret_cast<ull*>(bufA + q1 * 128 + 2 * (p + 8 * jj)) =
                pk(fmaxf(lo, 0.0f), fmaxf(hi, 0.0f));
            *reinterpret_cast<ull*>(bufF + q1 * 128 + 2 * (p + 8 * jj)) =
                pk((lo > 0.0f) ? tl : 0.0f, (hi > 0.0f) ? th : 0.0f);
        }
        __syncwarp();

        // ---- layer 2 fused (no relu): primal h1(A) -> z_dot(B),
        //      tangent h1'(F) -> zdot' (regs) -> div = <zdot', e>
#pragma unroll
        for (int jj = 0; jj < 8; jj++) {
            ull cvs = splat2(cv[128 + p + 8 * jj]);
            accP0[jj] = cvs; accP1[jj] = cvs;
            accT0[jj] = 0ull; accT1[jj] = 0ull;
        }
        gemv_fused(wf + 8704, A, F, p, accP0, accP1, accT0, accT1);
        ull dq0 = 0ull, dq1 = 0ull;
#pragma unroll
        for (int jj = 0; jj < 8; jj++) {
            *reinterpret_cast<ull*>(bufB + q0 * 128 + 2 * (p + 8 * jj)) = accP0[jj];
            *reinterpret_cast<ull*>(bufB + q1 * 128 + 2 * (p + 8 * jj)) = accP1[jj];
            ffma2(dq0, accT0[jj],
                  *reinterpret_cast<const ull*>(bufE + q0 * 128 + 2 * (p + 8 * jj)));
            ffma2(dq1, accT1[jj],
                  *reinterpret_cast<const ull*>(bufE + q1 * 128 + 2 * (p + 8 * jj)));
        }
        __syncwarp();

        // ---- flush z_dot: deinterleave B -> global (coalesced)
#pragma unroll 1
        for (int it = 0; it < 4; it++) {
            const int pairI = w * 8 + it * 2 + (lane >> 4);
            const int c     = lane & 15;
            u64x2 v1 = *reinterpret_cast<const u64x2*>(bufB + pairI * 128 + 8 * c);
            u64x2 v2 = *reinterpret_cast<const u64x2*>(bufB + pairI * 128 + 8 * c + 4);
            float4 ra, rb;
            unpk(v1.a, ra.x, rb.x); unpk(v1.b, ra.y, rb.y);
            unpk(v2.a, ra.z, rb.z); unpk(v2.b, ra.w, rb.w);
            const size_t g0 = (size_t)(rowBase + 2 * pairI) * 64 + 4 * c;
            *reinterpret_cast<float4*>(out + g0)      = ra;
            *reinterpret_cast<float4*>(out + g0 + 64) = rb;
        }

        // ---- reduce div over the 8-lane group, write -div
        float d0, d1, d2, d3;
        unpk(dq0, d0, d1);
        unpk(dq1, d2, d3);
#pragma unroll
        for (int ofs = 4; ofs > 0; ofs >>= 1) {
            d0 += __shfl_down_sync(0xffffffffu, d0, ofs, 8);
            d1 += __shfl_down_sync(0xffffffffu, d1, ofs, 8);
            d2 += __shfl_down_sync(0xffffffffu, d2, ofs, 8);
            d3 += __shfl_down_sync(0xffffffffu, d3, ofs, 8);
        }
        if (p == 0) {
            outD[rowBase + 4 * g + 0] = -d0;
            outD[rowBase + 4 * g + 1] = -d1;
            outD[rowBase + 4 * g + 2] = -d2;
            outD[rowBase + 4 * g + 3] = -d3;
        }
        __syncwarp();
    }
}

extern "C" void kernel_launch(void* const* d_in, const int* in_sizes, int n_in,
                              void* d_out, int out_size) {
    // metadata order: t, z, e, W0, b0, W1, b1, W2, b2 (all float32)
    const float* t  = (const float*)d_in[0];
    const float* z  = (const float*)d_in[1];
    const float* e  = (const float*)d_in[2];
    const float* W0 = (const float*)d_in[3];
    const float* b0 = (const float*)d_in[4];
    const float* W1 = (const float*)d_in[5];
    const float* b1 = (const float*)d_in[6];
    const float* W2 = (const float*)d_in[7];
    const float* b2 = (const float*)d_in[8];
    float* out = (float*)d_out;   // [B*64] z_dot followed by [B] of -div

    (void)in_sizes; (void)n_in; (void)out_size;

    cudaFuncSetAttribute(ode_kernel,
                         cudaFuncAttributeMaxDynamicSharedMemorySize, SMEM_BYTES);

    int dev = 0;
    cudaGetDevice(&dev);
    int sms = 148;
    cudaDeviceGetAttribute(&sms, cudaDevAttrMultiProcessorCount, dev);
    if (sms < 1) sms = 148;
    if (sms > NPASS) sms = NPASS;

    ode_kernel<<<sms, NT, SMEM_BYTES>>>(t, z, e, W0, b0, W1, b1, W2, b2, out);
}

// round 16
// speedup vs baseline: 1.9637x; 1.0222x over previous
#include <cuda_runtime.h>
#include <cstddef>

// Problem constants
#define BTOT   262144
#define NT     256          // threads per CTA (8 warps, 2 per SMSP)
#define NROWS  128          // rows per tile (32 groups of 8 threads x 4 rows)
#define NPASS  (BTOT / NROWS)   // 2048
#define WSTR   68           // weight SMEM row stride in floats (16B aligned, conflict-free)

// SMEM layout (floats) -- JVP formulation: forward weights ONLY
// wf[3]:  wf[l][j*WSTR+k] = W_l[j][k+1]                              (13056)
// cv[3][64]: b + t*W[:,0] folded (fwd layer 2 init)                  (192)
// iv[2][64]: fma(t, W_l[j][0], 0) chain-start for seq layers 0,1    (128)
// bia[2][64]: b_l[j] for seq layers 0,1 (added after chain)          (128)
// bufA/bufB: primal ping-pong, bufE: e (preserved), bufF: tangent
//   INTERLEAVED row-pair buffers: [64 pairs][64 k][2]                (4*8192)
#define OFF_C    13056
#define OFF_IV   13248
#define OFF_BIA  13376
#define OFF_A    13504
#define OFF_B    21696
#define OFF_E    29888
#define OFF_F    38080
#define SMEM_FLOATS 46272
#define SMEM_BYTES  (SMEM_FLOATS * 4)   // 185,088 B

typedef unsigned long long ull;
struct __align__(16) u64x2 { ull a, b; };

// packed fp32x2 FMA: two INDEPENDENT IEEE fp32 fma ops (lo, hi halves).
// Halves = (row_i, row_{i+1}): each half is a bit-exact sequential chain.
__device__ __forceinline__ void ffma2(ull& d, ull x, ull y) {
    asm("fma.rn.f32x2 %0, %1, %2, %0;" : "+l"(d) : "l"(x), "l"(y));
}
__device__ __forceinline__ ull addf2(ull a, ull b) {
    ull r; asm("add.rn.f32x2 %0, %1, %2;" : "=l"(r) : "l"(a), "l"(b)); return r;
}
__device__ __forceinline__ ull splat2(float f) {
    ull r; asm("mov.b64 %0, {%1, %1};" : "=l"(r) : "f"(f)); return r;
}
__device__ __forceinline__ ull pk(float lo, float hi) {
    ull r; asm("mov.b64 %0, {%1, %2};" : "=l"(r) : "f"(lo), "f"(hi)); return r;
}
__device__ __forceinline__ void unpk(ull v, float& lo, float& hi) {
    asm("mov.b64 {%0, %1}, %2;" : "=f"(lo), "=f"(hi) : "l"(v));
}

// One kb-step of activations for both streams (P: primal pairs 0/1, T: tangent)
struct Stage {
    u64x2 P0a, P0b, P1a, P1b, T0a, T0b, T1a, T1b;
};

__device__ __forceinline__ void ldstage(const float* __restrict__ aP,
                                        const float* __restrict__ aT,
                                        int kb, Stage& s) {
    s.P0a = *reinterpret_cast<const u64x2*>(aP + 8 * kb);
    s.P0b = *reinterpret_cast<const u64x2*>(aP + 8 * kb + 4);
    s.P1a = *reinterpret_cast<const u64x2*>(aP + 128 + 8 * kb);
    s.P1b = *reinterpret_cast<const u64x2*>(aP + 128 + 8 * kb + 4);
    s.T0a = *reinterpret_cast<const u64x2*>(aT + 8 * kb);
    s.T0b = *reinterpret_cast<const u64x2*>(aT + 8 * kb + 4);
    s.T1a = *reinterpret_cast<const u64x2*>(aT + 128 + 8 * kb);
    s.T1b = *reinterpret_cast<const u64x2*>(aT + 128 + 8 * kb + 4);
}

// Compute one kb-step: 8 weight float4 loads (slide across jj), 128 ffma2.
__device__ __forceinline__ void cstep(const float* __restrict__ mrow, int kb,
                                      const Stage& s,
                                      ull accP0[8], ull accP1[8],
                                      ull accT0[8], ull accT1[8]) {
#pragma unroll
    for (int jj = 0; jj < 8; jj++) {
        const float4 wv =
            *reinterpret_cast<const float4*>(mrow + jj * (8 * WSTR) + 4 * kb);
        ull wx = splat2(wv.x), wy = splat2(wv.y);
        ull wz = splat2(wv.z), ww = splat2(wv.w);
        ffma2(accP0[jj], s.P0a.a, wx);
        ffma2(accP0[jj], s.P0a.b, wy);
        ffma2(accP0[jj], s.P0b.a, wz);
        ffma2(accP0[jj], s.P0b.b, ww);
        ffma2(accP1[jj], s.P1a.a, wx);
        ffma2(accP1[jj], s.P1a.b, wy);
        ffma2(accP1[jj], s.P1b.a, wz);
        ffma2(accP1[jj], s.P1b.b, ww);
        ffma2(accT0[jj], s.T0a.a, wx);
        ffma2(accT0[jj], s.T0a.b, wy);
        ffma2(accT0[jj], s.T0b.a, wz);
        ffma2(accT0[jj], s.T0b.b, ww);
        ffma2(accT1[jj], s.T1a.a, wx);
        ffma2(accT1[jj], s.T1a.b, wy);
        ffma2(accT1[jj], s.T1b.a, wz);
        ffma2(accT1[jj], s.T1b.b, ww);
    }
}

// Fused primal+tangent GEMV, software-pipelined: act loads for step kb+1 are
// issued before the FMA block for step kb, hiding LDS latency at iteration
// boundaries. Arithmetic order identical to the non-pipelined version:
// each f32x2 half remains a strictly sequential ascending-k fp32 chain.
__device__ __forceinline__ void gemv_fused(const float* __restrict__ M,
                                           const float* __restrict__ aP,
                                           const float* __restrict__ aT,
                                           int p,
                                           ull accP0[8], ull accP1[8],
                                           ull accT0[8], ull accT1[8]) {
    const float* mrow = M + p * WSTR;
    Stage s0, s1;
    ldstage(aP, aT, 0, s0);
#pragma unroll 1
    for (int kb = 0; kb < 14; kb += 2) {
        ldstage(aP, aT, kb + 1, s1);
        cstep(mrow, kb, s0, accP0, accP1, accT0, accT1);
        ldstage(aP, aT, kb + 2, s0);
        cstep(mrow, kb + 1, s1, accP0, accP1, accT0, accT1);
    }
    ldstage(aP, aT, 15, s1);
    cstep(mrow, 14, s0, accP0, accP1, accT0, accT1);
    cstep(mrow, 15, s1, accP0, accP1, accT0, accT1);
}

__global__ void __launch_bounds__(NT, 1)
ode_kernel(const float* __restrict__ gt, const float* __restrict__ gz,
           const float* __restrict__ ge,
           const float* __restrict__ W0, const float* __restrict__ b0,
           const float* __restrict__ W1, const float* __restrict__ b1,
           const float* __restrict__ W2, const float* __restrict__ b2,
           float* __restrict__ out) {
    extern __shared__ float sm[];
    float* wf   = sm;
    float* cv   = sm + OFF_C;
    float* iv   = sm + OFF_IV;
    float* bia  = sm + OFF_BIA;
    float* bufA = sm + OFF_A;
    float* bufB = sm + OFF_B;
    float* bufE = sm + OFF_E;
    float* bufF = sm + OFF_F;

    const int tid = threadIdx.x;
    const float tval = gt[0];

    // ---- stage forward weights only
    const float* Ws[3] = {W0, W1, W2};
#pragma unroll 1
    for (int l = 0; l < 3; l++) {
        const float* W = Ws[l];
        for (int idx = tid; idx < 64 * 64; idx += NT) {
            int j = idx >> 6, k = idx & 63;
            wf[l * 4352 + j * WSTR + k] = W[j * 65 + k + 1];
        }
    }
    if (tid < 192) {
        int l = tid >> 6, j = tid & 63;
        const float* W  = Ws[l];
        const float* bb = (l == 0) ? b0 : (l == 1) ? b1 : b2;
        cv[tid] = bb[j] + tval * W[j * 65];
    }
    if (tid < 128) {
        int l = tid >> 6, j = tid & 63;
        const float* W  = l ? W1 : W0;
        iv[tid]  = __fmaf_rn(tval, W[j * 65], 0.0f);  // exact chain-start
        bia[tid] = l ? b1[j] : b0[j];
    }
    __syncthreads();

    const int p    = tid & 7;        // output slot within group
    const int g    = tid >> 3;       // group id (0..31), owns rows 4g..4g+3
    const int q0   = 2 * g;          // pair 0 = rows 4g, 4g+1
    const int q1   = 2 * g + 1;      // pair 1 = rows 4g+2, 4g+3
    const int w    = tid >> 5;       // warp id (owns pairs 8w..8w+7)
    const int lane = tid & 31;

    const float* A = bufA + q0 * 128;
    const float* B = bufB + q0 * 128;
    const float* E = bufE + q0 * 128;
    const float* F = bufF + q0 * 128;
    float* outD = out + (size_t)BTOT * 64;

    for (int tile = blockIdx.x; tile < NPASS; tile += gridDim.x) {
        const int rowBase = tile * NROWS;

        // ---- stage z -> bufA, e -> bufE, interleaved by row pair (warp-local)
#pragma unroll 1
        for (int it = 0; it < 4; it++) {
            const int pairI = w * 8 + it * 2 + (lane >> 4);
            const int c     = lane & 15;
            const size_t g0 = (size_t)(rowBase + 2 * pairI) * 64 + 4 * c;
            float4 za = *reinterpret_cast<const float4*>(gz + g0);
            float4 zb = *reinterpret_cast<const float4*>(gz + g0 + 64);
            u64x2 v1, v2;
            v1.a = pk(za.x, zb.x); v1.b = pk(za.y, zb.y);
            v2.a = pk(za.z, zb.z); v2.b = pk(za.w, zb.w);
            *reinterpret_cast<u64x2*>(bufA + pairI * 128 + 8 * c)     = v1;
            *reinterpret_cast<u64x2*>(bufA + pairI * 128 + 8 * c + 4) = v2;
            float4 ea = *reinterpret_cast<const float4*>(ge + g0);
            float4 eb = *reinterpret_cast<const float4*>(ge + g0 + 64);
            v1.a = pk(ea.x, eb.x); v1.b = pk(ea.y, eb.y);
            v2.a = pk(ea.z, eb.z); v2.b = pk(ea.w, eb.w);
            *reinterpret_cast<u64x2*>(bufE + pairI * 128 + 8 * c)     = v1;
            *reinterpret_cast<u64x2*>(bufE + pairI * 128 + 8 * c + 4) = v2;
        }
        __syncwarp();

        ull accP0[8], accP1[8], accT0[8], accT1[8];

        // ---- layer 0 fused: primal z(A) -> h0(B) [ref-order chain],
        //                     tangent e(E) -> h0'(F) [masked by primal sign]
#pragma unroll
        for (int jj = 0; jj < 8; jj++) {
            ull ivs = splat2(iv[p + 8 * jj]);
            accP0[jj] = ivs; accP1[jj] = ivs;
            accT0[jj] = 0ull; accT1[jj] = 0ull;
        }
        gemv_fused(wf, A, E, p, accP0, accP1, accT0, accT1);
#pragma unroll
        for (int jj = 0; jj < 8; jj++) {
            ull bsp = splat2(bia[p + 8 * jj]);
            float lo, hi, tl, th;
            unpk(addf2(accP0[jj], bsp), lo, hi);
            unpk(accT0[jj], tl, th);
            *reinterpret_cast<ull*>(bufB + q0 * 128 + 2 * (p + 8 * jj)) =
                pk(fmaxf(lo, 0.0f), fmaxf(hi, 0.0f));
            *reinterpret_cast<ull*>(bufF + q0 * 128 + 2 * (p + 8 * jj)) =
                pk((lo > 0.0f) ? tl : 0.0f, (hi > 0.0f) ? th : 0.0f);
            unpk(addf2(accP1[jj], bsp), lo, hi);
            unpk(accT1[jj], tl, th);
            *reinterpret_cast<ull*>(bufB + q1 * 128 + 2 * (p + 8 * jj)) =
                pk(fmaxf(lo, 0.0f), fmaxf(hi, 0.0f));
            *reinterpret_cast<ull*>(bufF + q1 * 128 + 2 * (p + 8 * jj)) =
                pk((lo > 0.0f) ? tl : 0.0f, (hi > 0.0f) ? th : 0.0f);
        }
        __syncwarp();

        // ---- layer 1 fused: primal h0(B) -> h1(A), tangent h0'(F) -> h1'(F)
#pragma unroll
        for (int jj = 0; jj < 8; jj++) {
            ull ivs = splat2(iv[64 + p + 8 * jj]);
            accP0[jj] = ivs; accP1[jj] = ivs;
            accT0[jj] = 0ull; accT1[jj] = 0ull;
        }
        gemv_fused(wf + 4352, B, F, p, accP0, accP1, accT0, accT1);
#pragma unroll
        for (int jj = 0; jj < 8; jj++) {
            ull bsp = splat2(bia[64 + p + 8 * jj]);
            float lo, hi, tl, th;
            unpk(addf2(accP0[jj], bsp), lo, hi);
            unpk(accT0[jj], tl, th);
            *reinterpret_cast<ull*>(bufA + q0 * 128 + 2 * (p + 8 * jj)) =
                pk(fmaxf(lo, 0.0f), fmaxf(hi, 0.0f));
            *reinterpret_cast<ull*>(bufF + q0 * 128 + 2 * (p + 8 * jj)) =
                pk((lo > 0.0f) ? tl : 0.0f, (hi > 0.0f) ? th : 0.0f);
            unpk(addf2(accP1[jj], bsp), lo, hi);
            unpk(accT1[jj], tl, th);
            *reinterpret_cast<ull*>(bufA + q1 * 128 + 2 * (p + 8 * jj)) =
                pk(fmaxf(lo, 0.0f), fmaxf(hi, 0.0f));
            *reinterpret_cast<ull*>(bufF + q1 * 128 + 2 * (p + 8 * jj)) =
                pk((lo > 0.0f) ? tl : 0.0f, (hi > 0.0f) ? th : 0.0f);
        }
        __syncwarp();

        // ---- layer 2 fused (no relu): primal h1(A) -> z_dot(B),
        //      tangent h1'(F) -> zdot' (regs) -> div = <zdot', e>
#pragma unroll
        for (int jj = 0; jj < 8; jj++) {
            ull cvs = splat2(cv[128 + p + 8 * jj]);
            accP0[jj] = cvs; accP1[jj] = cvs;
            accT0[jj] = 0ull; accT1[jj] = 0ull;
        }
        gemv_fused(wf + 8704, A, F, p, accP0, accP1, accT0, accT1);
        ull dq0 = 0ull, dq1 = 0ull;
#pragma unroll
        for (int jj = 0; jj < 8; jj++) {
            *reinterpret_cast<ull*>(bufB + q0 * 128 + 2 * (p + 8 * jj)) = accP0[jj];
            *reinterpret_cast<ull*>(bufB + q1 * 128 + 2 * (p + 8 * jj)) = accP1[jj];
            ffma2(dq0, accT0[jj],
                  *reinterpret_cast<const ull*>(bufE + q0 * 128 + 2 * (p + 8 * jj)));
            ffma2(dq1, accT1[jj],
                  *reinterpret_cast<const ull*>(bufE + q1 * 128 + 2 * (p + 8 * jj)));
        }
        __syncwarp();

        // ---- flush z_dot: deinterleave B -> global (coalesced)
#pragma unroll 1
        for (int it = 0; it < 4; it++) {
            const int pairI = w * 8 + it * 2 + (lane >> 4);
            const int c     = lane & 15;
            u64x2 v1 = *reinterpret_cast<const u64x2*>(bufB + pairI * 128 + 8 * c);
            u64x2 v2 = *reinterpret_cast<const u64x2*>(bufB + pairI * 128 + 8 * c + 4);
            float4 ra, rb;
            unpk(v1.a, ra.x, rb.x); unpk(v1.b, ra.y, rb.y);
            unpk(v2.a, ra.z, rb.z); unpk(v2.b, ra.w, rb.w);
            const size_t g0 = (size_t)(rowBase + 2 * pairI) * 64 + 4 * c;
            *reinterpret_cast<float4*>(out + g0)      = ra;
            *reinterpret_cast<float4*>(out + g0 + 64) = rb;
        }

        // ---- reduce div over the 8-lane group, write -div
        float d0, d1, d2, d3;
        unpk(dq0, d0, d1);
        unpk(dq1, d2, d3);
#pragma unroll
        for (int ofs = 4; ofs > 0; ofs >>= 1) {
            d0 += __shfl_down_sync(0xffffffffu, d0, ofs, 8);
            d1 += __shfl_down_sync(0xffffffffu, d1, ofs, 8);
            d2 += __shfl_down_sync(0xffffffffu, d2, ofs, 8);
            d3 += __shfl_down_sync(0xffffffffu, d3, ofs, 8);
        }
        if (p == 0) {
            outD[rowBase + 4 * g + 0] = -d0;
            outD[rowBase + 4 * g + 1] = -d1;
            outD[rowBase + 4 * g + 2] = -d2;
            outD[rowBase + 4 * g + 3] = -d3;
        }
        __syncwarp();
    }
}

extern "C" void kernel_launch(void* const* d_in, const int* in_sizes, int n_in,
                              void* d_out, int out_size) {
    // metadata order: t, z, e, W0, b0, W1, b1, W2, b2 (all float32)
    const float* t  = (const float*)d_in[0];
    const float* z  = (const float*)d_in[1];
    const float* e  = (const float*)d_in[2];
    const float* W0 = (const float*)d_in[3];
    const float* b0 = (const float*)d_in[4];
    const float* W1 = (const float*)d_in[5];
    const float* b1 = (const float*)d_in[6];
    const float* W2 = (const float*)d_in[7];
    const float* b2 = (const float*)d_in[8];
    float* out = (float*)d_out;   // [B*64] z_dot followed by [B] of -div

    (void)in_sizes; (void)n_in; (void)out_size;

    cudaFuncSetAttribute(ode_kernel,
                         cudaFuncAttributeMaxDynamicSharedMemorySize, SMEM_BYTES);

    int dev = 0;
    cudaGetDevice(&dev);
    int sms = 148;
    cudaDeviceGetAttribute(&sms, cudaDevAttrMultiProcessorCount, dev);
    if (sms < 1) sms = 148;
    if (sms > NPASS) sms = NPASS;

    ode_kernel<<<sms, NT, SMEM_BYTES>>>(t, z, e, W0, b0, W1, b1, W2, b2, out);
}